// round 14
// baseline (speedup 1.0000x reference)
#include <cuda_runtime.h>

// GRU-ODE: B=32768 rows, T=28, DIM=H=32, 10-step RK4, RHS = 2-layer tanh MLP.
// R=8 rows/thread in rk4 (8 lanes/group, j-slice 4): 1 weight-LDS per k per
// 8 rows. State fully f32x2-packed (h/ks/acc u64): yt and z never exist in
// registers -- computed in the smem store phase. GRU runs as two 4-row halves
// with store-once x/h buffers. Weights 32KB + swizzled ybuf 16KB = 48KB smem.
// R10 fix: gru4 x-load had ooff added twice (caller pre-offset + callee).

#define TT 28
#define NSTEPS 10
typedef unsigned long long u64;

__device__ __forceinline__ u64 splat2(float x) {
    u64 d; asm("mov.b64 %0, {%1, %1};" : "=l"(d) : "f"(x)); return d;
}
__device__ __forceinline__ u64 pack2(float lo, float hi) {
    u64 d; asm("mov.b64 %0, {%1, %2};" : "=l"(d) : "f"(lo), "f"(hi)); return d;
}
__device__ __forceinline__ float2 unpack2(u64 v) {
    float2 r; asm("mov.b64 {%0, %1}, %2;" : "=f"(r.x), "=f"(r.y) : "l"(v)); return r;
}
__device__ __forceinline__ u64 fma2(u64 a, u64 b, u64 c) {
    u64 d; asm("fma.rn.f32x2 %0, %1, %2, %3;" : "=l"(d) : "l"(a), "l"(b), "l"(c)); return d;
}
__device__ __forceinline__ u64 add2(u64 a, u64 b) {
    u64 d; asm("add.rn.f32x2 %0, %1, %2;" : "=l"(d) : "l"(a), "l"(b)); return d;
}

__device__ __forceinline__ float sigmoidf_fast(float x) {
    return __fdividef(1.0f, 1.0f + __expf(-x));
}
__device__ __forceinline__ float tanhf_fast(float x) {
    return 1.0f - __fdividef(2.0f, 1.0f + __expf(2.0f * x));
}

// ── swizzled group buffer: 256 floats/group, chunk index (r*8 + k/4) ^ grp ──
__device__ __forceinline__ float4 ld4s(const float* __restrict__ gb, int grp, int chunk) {
    return *reinterpret_cast<const float4*>(gb + ((chunk ^ grp) << 2));
}
__device__ __forceinline__ void st4s(float* __restrict__ gb, int grp, int chunk,
                                     u64 a, u64 b) {
    *reinterpret_cast<ulonglong2*>(gb + ((chunk ^ grp) << 2)) = make_ulonglong2(a, b);
}

// acc[r] += y[r] @ T-slice, 8 rows, y read from swizzled group buffer.
__device__ __forceinline__ void mvload8(const float* __restrict__ T, int ooff, int grp,
                                        const float* __restrict__ gb, u64 (&a)[8][2]) {
#pragma unroll 1
    for (int src = 0; src < 8; ++src) {          // dynamic: bounds reg hoisting
        float ym[8][4];
#pragma unroll
        for (int r = 0; r < 8; ++r) {
            const float4 v = ld4s(gb, grp, r * 8 + src);
            ym[r][0] = v.x; ym[r][1] = v.y; ym[r][2] = v.z; ym[r][3] = v.w;
        }
        const int k0 = src * 4;
#pragma unroll
        for (int m = 0; m < 4; ++m) {
            const ulonglong2 w = *reinterpret_cast<const ulonglong2*>(T + (k0 + m) * 32 + ooff);
#pragma unroll
            for (int r = 0; r < 8; ++r) {
                const u64 s = splat2(ym[r][m]);
                a[r][0] = fma2(s, w.x, a[r][0]);
                a[r][1] = fma2(s, w.y, a[r][1]);
            }
        }
    }
}

// 4-row variant for GRU (row base rb within the group's 8 slots).
__device__ __forceinline__ void mvload4(const float* __restrict__ T, int ooff, int grp,
                                        const float* __restrict__ gb, int rb, u64 (&a)[4][2]) {
#pragma unroll 1
    for (int src = 0; src < 8; ++src) {
        float ym[4][4];
#pragma unroll
        for (int r = 0; r < 4; ++r) {
            const float4 v = ld4s(gb, grp, (rb + r) * 8 + src);
            ym[r][0] = v.x; ym[r][1] = v.y; ym[r][2] = v.z; ym[r][3] = v.w;
        }
        const int k0 = src * 4;
#pragma unroll
        for (int m = 0; m < 4; ++m) {
            const ulonglong2 w = *reinterpret_cast<const ulonglong2*>(T + (k0 + m) * 32 + ooff);
#pragma unroll
            for (int r = 0; r < 4; ++r) {
                const u64 s = splat2(ym[r][m]);
                a[r][0] = fma2(s, w.x, a[r][0]);
                a[r][1] = fma2(s, w.y, a[r][1]);
            }
        }
    }
}

// One RHS eval for 8 rows: on entry acc = k_prev (packed); stores yt = h + cn*k_prev
// (or h itself when FIRST), runs tanh-MLP, leaves acc = k_new.
template <bool FIRST>
__device__ __forceinline__ void rhs8(const float* __restrict__ T1, const float* __restrict__ T2,
                                     int ooff, int grp, float* __restrict__ gb,
                                     const u64 (&h)[8][2], u64 (&acc)[8][2], u64 cn2,
                                     u64 b1q0, u64 b1q1, u64 b2q0, u64 b2q1) {
    const int cb = ooff >> 2;
#pragma unroll
    for (int r = 0; r < 8; ++r) {
        u64 y0, y1;
        if (FIRST) { y0 = h[r][0]; y1 = h[r][1]; }
        else       { y0 = fma2(cn2, acc[r][0], h[r][0]); y1 = fma2(cn2, acc[r][1], h[r][1]); }
        st4s(gb, grp, r * 8 + cb, y0, y1);
    }
    __syncwarp();
#pragma unroll
    for (int r = 0; r < 8; ++r) { acc[r][0] = b1q0; acc[r][1] = b1q1; }
    mvload8(T1, ooff, grp, gb, acc);
    __syncwarp();
#pragma unroll
    for (int r = 0; r < 8; ++r) {
        const float2 v0 = unpack2(acc[r][0]);
        const float2 v1 = unpack2(acc[r][1]);
        st4s(gb, grp, r * 8 + cb,
             pack2(tanhf_fast(v0.x), tanhf_fast(v0.y)),
             pack2(tanhf_fast(v1.x), tanhf_fast(v1.y)));
    }
    __syncwarp();
#pragma unroll
    for (int r = 0; r < 8; ++r) { acc[r][0] = b2q0; acc[r][1] = b2q1; }
    mvload8(T2, ooff, grp, gb, acc);
    __syncwarp();
}

__device__ __forceinline__ void rk4_8(const float* __restrict__ T1, const float* __restrict__ T2,
                                      int ooff, int grp, float* __restrict__ gb,
                                      u64 (&h)[8][2], float span,
                                      u64 b1q0, u64 b1q1, u64 b2q0, u64 b2q1) {
    const float dt = span * (1.0f / NSTEPS);
    const u64 dth2 = splat2(0.5f * dt);
    const u64 dtf2 = splat2(dt);
    const u64 dt62 = splat2(dt * (1.0f / 6.0f));
    const u64 two2 = splat2(2.0f);
    const u64 one2 = splat2(1.0f);
#pragma unroll 1
    for (int st = 0; st < NSTEPS; ++st) {
        u64 acc[8][2], ks[8][2];
        rhs8<true>(T1, T2, ooff, grp, gb, h, acc, 0ull, b1q0, b1q1, b2q0, b2q1);
#pragma unroll
        for (int r = 0; r < 8; ++r) { ks[r][0] = acc[r][0]; ks[r][1] = acc[r][1]; }
        rhs8<false>(T1, T2, ooff, grp, gb, h, acc, dth2, b1q0, b1q1, b2q0, b2q1);
#pragma unroll
        for (int r = 0; r < 8; ++r) {
            ks[r][0] = fma2(two2, acc[r][0], ks[r][0]);
            ks[r][1] = fma2(two2, acc[r][1], ks[r][1]);
        }
        rhs8<false>(T1, T2, ooff, grp, gb, h, acc, dth2, b1q0, b1q1, b2q0, b2q1);
#pragma unroll
        for (int r = 0; r < 8; ++r) {
            ks[r][0] = fma2(two2, acc[r][0], ks[r][0]);
            ks[r][1] = fma2(two2, acc[r][1], ks[r][1]);
        }
        rhs8<false>(T1, T2, ooff, grp, gb, h, acc, dtf2, b1q0, b1q1, b2q0, b2q1);
#pragma unroll
        for (int r = 0; r < 8; ++r) {
            ks[r][0] = fma2(one2, acc[r][0], ks[r][0]);
            ks[r][1] = fma2(one2, acc[r][1], ks[r][1]);
            h[r][0]  = fma2(dt62, ks[r][0], h[r][0]);
            h[r][1]  = fma2(dt62, ks[r][1], h[r][1]);
        }
    }
}

// PyTorch-order GRU (r,z,n) on 4 rows. x stored to slots 0..3, h to slots 4..7,
// once; then 6 matvecs read them (no intermediate stores).
// NOTE: xg is already offset by ooff by the caller -- do NOT add ooff here.
__device__ __forceinline__ void gru4(const float* __restrict__ Tw, int ooff, int grp,
                                     float* __restrict__ gb, u64 (*h4)[2],
                                     const float* __restrict__ xg, int t,
                                     const float* __restrict__ bih,
                                     const float* __restrict__ bhh) {
    const int cb = ooff >> 2;
#pragma unroll
    for (int r = 0; r < 4; ++r) {
        const float4 xv = *reinterpret_cast<const float4*>(xg + (size_t)r * TT * 32 + t * 32);
        st4s(gb, grp, r * 8 + cb, pack2(xv.x, xv.y), pack2(xv.z, xv.w));
        st4s(gb, grp, (4 + r) * 8 + cb, h4[r][0], h4[r][1]);
    }
    __syncwarp();

    const float* Tih = Tw + 2048;
    const float* Thh = Tw + 5120;

    u64 a1[4][2], a2[4][2], rg[4][2], zg[4][2];
    // r gate
    {
        const float4 bi = *reinterpret_cast<const float4*>(bih + ooff);
        const float4 bh = *reinterpret_cast<const float4*>(bhh + ooff);
        const u64 b0 = add2(pack2(bi.x, bi.y), pack2(bh.x, bh.y));
        const u64 b1 = add2(pack2(bi.z, bi.w), pack2(bh.z, bh.w));
#pragma unroll
        for (int r = 0; r < 4; ++r) { a1[r][0] = b0; a1[r][1] = b1; }
    }
    mvload4(Tih + 0 * 1024, ooff, grp, gb, 0, a1);
    mvload4(Thh + 0 * 1024, ooff, grp, gb, 4, a1);
#pragma unroll
    for (int r = 0; r < 4; ++r)
#pragma unroll
        for (int p = 0; p < 2; ++p) {
            const float2 v = unpack2(a1[r][p]);
            rg[r][p] = pack2(sigmoidf_fast(v.x), sigmoidf_fast(v.y));
        }
    // z gate
    {
        const float4 bi = *reinterpret_cast<const float4*>(bih + 32 + ooff);
        const float4 bh = *reinterpret_cast<const float4*>(bhh + 32 + ooff);
        const u64 b0 = add2(pack2(bi.x, bi.y), pack2(bh.x, bh.y));
        const u64 b1 = add2(pack2(bi.z, bi.w), pack2(bh.z, bh.w));
#pragma unroll
        for (int r = 0; r < 4; ++r) { a1[r][0] = b0; a1[r][1] = b1; }
    }
    mvload4(Tih + 1 * 1024, ooff, grp, gb, 0, a1);
    mvload4(Thh + 1 * 1024, ooff, grp, gb, 4, a1);
#pragma unroll
    for (int r = 0; r < 4; ++r)
#pragma unroll
        for (int p = 0; p < 2; ++p) {
            const float2 v = unpack2(a1[r][p]);
            zg[r][p] = pack2(sigmoidf_fast(v.x), sigmoidf_fast(v.y));
        }
    // n gate: input part (a1), hidden part (a2)
    {
        const float4 bi = *reinterpret_cast<const float4*>(bih + 64 + ooff);
        const float4 bh = *reinterpret_cast<const float4*>(bhh + 64 + ooff);
        const u64 i0 = pack2(bi.x, bi.y), i1 = pack2(bi.z, bi.w);
        const u64 h0v = pack2(bh.x, bh.y), h1v = pack2(bh.z, bh.w);
#pragma unroll
        for (int r = 0; r < 4; ++r) {
            a1[r][0] = i0;  a1[r][1] = i1;
            a2[r][0] = h0v; a2[r][1] = h1v;
        }
    }
    mvload4(Tih + 2 * 1024, ooff, grp, gb, 0, a1);
    mvload4(Thh + 2 * 1024, ooff, grp, gb, 4, a2);
#pragma unroll
    for (int r = 0; r < 4; ++r)
#pragma unroll
        for (int p = 0; p < 2; ++p) {
            const float2 gi = unpack2(a1[r][p]);
            const float2 gh = unpack2(a2[r][p]);
            const float2 rr = unpack2(rg[r][p]);
            const float2 zz = unpack2(zg[r][p]);
            const float2 hh = unpack2(h4[r][p]);
            const float n0 = tanhf_fast(gi.x + rr.x * gh.x);
            const float n1 = tanhf_fast(gi.y + rr.y * gh.y);
            h4[r][p] = pack2(n0 + zz.x * (hh.x - n0), n1 + zz.y * (hh.y - n1));
        }
    __syncwarp();
}

extern "C" __global__ void __launch_bounds__(128, 3)
ode_gru_kernel(const float* __restrict__ inputs, const float* __restrict__ h0,
               const float* __restrict__ Wih, const float* __restrict__ Whh,
               const float* __restrict__ bih, const float* __restrict__ bhh,
               const float* __restrict__ W1, const float* __restrict__ b1,
               const float* __restrict__ W2, const float* __restrict__ b2,
               float* __restrict__ out, int B) {
    // Tw layout (floats): [0..1024)=T1, [1024..2048)=T2,
    // [2048..5120)=Tih[3], [5120..8192)=Thh[3]; all transposed T[k*32+j]=W[j*32+k].
    __shared__ __align__(16) float Tw[8192];
    __shared__ __align__(16) float ybuf[16 * 256];

    for (int i = threadIdx.x; i < 1024; i += blockDim.x) {
        const int j = i >> 5, k = i & 31;
        Tw[k * 32 + j]        = W1[i];
        Tw[1024 + k * 32 + j] = W2[i];
    }
    for (int i = threadIdx.x; i < 3072; i += blockDim.x) {
        const int g = i >> 10, r = (i >> 5) & 31, k = i & 31;
        Tw[2048 + g * 1024 + k * 32 + r] = Wih[i];
        Tw[5120 + g * 1024 + k * 32 + r] = Whh[i];
    }
    __syncthreads();

    const int gt   = blockIdx.x * blockDim.x + threadIdx.x;
    const int grp8 = gt >> 3;            // 8-row group index
    const int ooff = (gt & 7) * 4;       // j-slice offset
    const int row0 = grp8 * 8;
    if (row0 >= B) return;               // B % 32 == 0: warp-uniform

    const int grp = (threadIdx.x >> 3) & 3;          // group-in-warp (swizzle key)
    float* gb = ybuf + (threadIdx.x >> 3) * 256;

    // biases for the MLP in registers
    u64 b1q0, b1q1, b2q0, b2q1;
    {
        const float4 v1 = *reinterpret_cast<const float4*>(b1 + ooff);
        const float4 v2 = *reinterpret_cast<const float4*>(b2 + ooff);
        b1q0 = pack2(v1.x, v1.y); b1q1 = pack2(v1.z, v1.w);
        b2q0 = pack2(v2.x, v2.y); b2q1 = pack2(v2.z, v2.w);
    }

    u64 h[8][2];
#pragma unroll
    for (int r = 0; r < 8; ++r) {
        const float4 v = *reinterpret_cast<const float4*>(h0 + (size_t)(row0 + r) * 32 + ooff);
        h[r][0] = pack2(v.x, v.y); h[r][1] = pack2(v.z, v.w);
    }

    const float* xg0 = inputs + (size_t)row0 * TT * 32 + ooff;        // rows 0..3
    const float* xg1 = inputs + (size_t)(row0 + 4) * TT * 32 + ooff;  // rows 4..7

    // initial integration over [0, 1]
    rk4_8(Tw, Tw + 1024, ooff, grp, gb, h, 1.0f, b1q0, b1q1, b2q0, b2q1);

#pragma unroll 1
    for (int t = 0; t < TT; ++t) {
        gru4(Tw, ooff, grp, gb, &h[0], xg0, t, bih, bhh);
        gru4(Tw, ooff, grp, gb, &h[4], xg1, t, bih, bhh);
        if (t < TT - 1)
            rk4_8(Tw, Tw + 1024, ooff, grp, gb, h, 1.0f, b1q0, b1q1, b2q0, b2q1);
    }

    // h_start -> out[0], then 14-unit integration -> out[1]
#pragma unroll
    for (int r = 0; r < 8; ++r) {
        const float2 v0 = unpack2(h[r][0]);
        const float2 v1 = unpack2(h[r][1]);
        *reinterpret_cast<float4*>(out + (size_t)(row0 + r) * 32 + ooff) =
            make_float4(fmaxf(v0.x, 0.0f), fmaxf(v0.y, 0.0f),
                        fmaxf(v1.x, 0.0f), fmaxf(v1.y, 0.0f));
    }
    rk4_8(Tw, Tw + 1024, ooff, grp, gb, h, 14.0f, b1q0, b1q1, b2q0, b2q1);
#pragma unroll
    for (int r = 0; r < 8; ++r) {
        const float2 v0 = unpack2(h[r][0]);
        const float2 v1 = unpack2(h[r][1]);
        *reinterpret_cast<float4*>(out + (size_t)B * 32 + (size_t)(row0 + r) * 32 + ooff) =
            make_float4(fmaxf(v0.x, 0.0f), fmaxf(v0.y, 0.0f),
                        fmaxf(v1.x, 0.0f), fmaxf(v1.y, 0.0f));
    }
}

extern "C" void kernel_launch(void* const* d_in, const int* in_sizes, int n_in,
                              void* d_out, int out_size) {
    const float* inputs = (const float*)d_in[0];
    const float* h0     = (const float*)d_in[1];
    const float* Wih    = (const float*)d_in[2];
    const float* Whh    = (const float*)d_in[3];
    const float* bih    = (const float*)d_in[4];
    const float* bhh    = (const float*)d_in[5];
    const float* W1     = (const float*)d_in[6];
    const float* b1     = (const float*)d_in[7];
    const float* W2     = (const float*)d_in[8];
    const float* b2     = (const float*)d_in[9];

    const int B = in_sizes[1] / 32;          // h0 is [B, 32]
    const int threads = 128;
    const long total = ((long)B / 8) * 8;    // 8 threads per 8-row group = B threads
    const int blocks = (int)((total + threads - 1) / threads);
    ode_gru_kernel<<<blocks, threads>>>(inputs, h0, Wih, Whh, bih, bhh,
                                        W1, b1, W2, b2, (float*)d_out, B);
}